// round 3
// baseline (speedup 1.0000x reference)
#include <cuda_runtime.h>

// Problem constants
#define Bn 4
#define Ln 8
#define Nn 4096
#define Mn 2048
#define Kn 32
#define Sn 8
#define Jn 3

// Staging buffers (device globals; no runtime allocation)
__device__ float g_anchors[Bn * Sn * Mn * 3];            // anchor coords
__device__ float g_P[Bn * 8 * Nn * 64];                  // Ws0[:,:3]@xyz + Ws0[:,3:]@feat per point
__device__ float g_A[Bn * Sn * Mn * 64];                 // Ws0[:,:3]@anchor
__device__ int   g_idx[Bn * Sn * Jn * Mn * Kn];          // ball query result
__device__ float g_hmax[Bn * Sn * Jn * Mn * 128];        // [combo][m][r] max-pooled layer-1 out
__device__ float g_WtT[Jn * 128 * 256];                  // Wt transposed [j][r][o]
__device__ float g_Ws1T[64 * 128];                       // Ws1 transposed [k][r]

// ---------------------------------------------------------------------------
// K1: Furthest point sampling. One block per (b, s). 1024 threads, 4 pts each,
// coords carried through the argmax reduction (2 barriers/iter).
// Arithmetic matches XLA: ((dx*dx + dy*dy) + dz*dz), no FMA contraction.
// argmax tie-break: smallest index.
// ---------------------------------------------------------------------------
__global__ void __launch_bounds__(1024) fps_kernel(const float* __restrict__ xyzs,
                                                   float* __restrict__ out_xyz) {
    int bs = blockIdx.x;
    const float* xyz = xyzs + (size_t)bs * Nn * 3;
    __shared__ float rv[32], rx[32], ry[32], rz[32];
    __shared__ int ri[32];
    __shared__ float scx, scy, scz;

    int t = threadIdx.x;
    int lane = t & 31, wid = t >> 5;

    float px[4], py[4], pz[4], pd[4];
#pragma unroll
    for (int i = 0; i < 4; i++) {
        int p = t + i * 1024;
        px[i] = xyz[3 * p]; py[i] = xyz[3 * p + 1]; pz[i] = xyz[3 * p + 2];
        pd[i] = 1e10f;
    }
    if (t == 0) { scx = px[0]; scy = py[0]; scz = pz[0]; }
    __syncthreads();

    float* oanc = g_anchors + (size_t)bs * Mn * 3;
    float* oxyz = out_xyz + (size_t)bs * Mn * 3;

    for (int m = 0; m < Mn; m++) {
        float cx = scx, cy = scy, cz = scz;
        if (t == 0) {
            oanc[3 * m] = cx; oanc[3 * m + 1] = cy; oanc[3 * m + 2] = cz;
            oxyz[3 * m] = cx; oxyz[3 * m + 1] = cy; oxyz[3 * m + 2] = cz;
        }
        float best = -1.0f, bx = 0.f, by = 0.f, bz = 0.f;
        int bi = 0;
#pragma unroll
        for (int i = 0; i < 4; i++) {
            float dx = __fsub_rn(px[i], cx);
            float dy = __fsub_rn(py[i], cy);
            float dz = __fsub_rn(pz[i], cz);
            float d = __fadd_rn(__fadd_rn(__fmul_rn(dx, dx), __fmul_rn(dy, dy)),
                                __fmul_rn(dz, dz));
            float nd = fminf(pd[i], d);
            pd[i] = nd;
            if (nd > best) { best = nd; bi = t + i * 1024; bx = px[i]; by = py[i]; bz = pz[i]; }
        }
#pragma unroll
        for (int off = 16; off > 0; off >>= 1) {
            float v = __shfl_xor_sync(0xffffffffu, best, off);
            int j2 = __shfl_xor_sync(0xffffffffu, bi, off);
            float x2 = __shfl_xor_sync(0xffffffffu, bx, off);
            float y2 = __shfl_xor_sync(0xffffffffu, by, off);
            float z2 = __shfl_xor_sync(0xffffffffu, bz, off);
            if (v > best || (v == best && j2 < bi)) { best = v; bi = j2; bx = x2; by = y2; bz = z2; }
        }
        if (lane == 0) { rv[wid] = best; ri[wid] = bi; rx[wid] = bx; ry[wid] = by; rz[wid] = bz; }
        __syncthreads();
        if (wid == 0) {
            best = rv[lane]; bi = ri[lane]; bx = rx[lane]; by = ry[lane]; bz = rz[lane];
#pragma unroll
            for (int off = 16; off > 0; off >>= 1) {
                float v = __shfl_xor_sync(0xffffffffu, best, off);
                int j2 = __shfl_xor_sync(0xffffffffu, bi, off);
                float x2 = __shfl_xor_sync(0xffffffffu, bx, off);
                float y2 = __shfl_xor_sync(0xffffffffu, by, off);
                float z2 = __shfl_xor_sync(0xffffffffu, bz, off);
                if (v > best || (v == best && j2 < bi)) { best = v; bi = j2; bx = x2; by = y2; bz = z2; }
            }
            if (lane == 0) { scx = bx; scy = by; scz = bz; }
        }
        __syncthreads();
    }
}

// ---------------------------------------------------------------------------
// K2a: P[b][f][n][64] = Ws0[:,0:3] @ xyz + Ws0[:,3:6] @ feat
// ---------------------------------------------------------------------------
__global__ void __launch_bounds__(256) compute_P(const float* __restrict__ xyzs,
                                                 const float* __restrict__ feats,
                                                 const float* __restrict__ Ws0) {
    __shared__ float w[64 * 6];
    int t = threadIdx.x;
    for (int i = t; i < 64 * 6; i += 256) w[i] = Ws0[i];
    __syncthreads();

    int gp = blockIdx.x * 256 + t;
    int n = gp & (Nn - 1);
    int bf = gp >> 12;
    const float* p = xyzs + (size_t)gp * 3;
    float x = p[0], y = p[1], z = p[2];
    const float* f = feats + (size_t)bf * 3 * Nn + n;
    float f0 = f[0], f1 = f[Nn], f2 = f[2 * Nn];
    float4* o = (float4*)(g_P + (size_t)gp * 64);
#pragma unroll
    for (int oo = 0; oo < 64; oo += 4) {
        float4 r;
        const float* w0 = w + oo * 6;
        r.x = w0[0] * x + w0[1] * y + w0[2] * z + w0[3] * f0 + w0[4] * f1 + w0[5] * f2;
        r.y = w0[6] * x + w0[7] * y + w0[8] * z + w0[9] * f0 + w0[10] * f1 + w0[11] * f2;
        r.z = w0[12] * x + w0[13] * y + w0[14] * z + w0[15] * f0 + w0[16] * f1 + w0[17] * f2;
        r.w = w0[18] * x + w0[19] * y + w0[20] * z + w0[21] * f0 + w0[22] * f1 + w0[23] * f2;
        o[oo >> 2] = r;
    }
}

// ---------------------------------------------------------------------------
// K2b: A[b][s][m][64] = Ws0[:,0:3] @ anchor
// ---------------------------------------------------------------------------
__global__ void __launch_bounds__(256) compute_A(const float* __restrict__ Ws0) {
    __shared__ float w[64 * 3];
    int t = threadIdx.x;
    for (int i = t; i < 64 * 3; i += 256) {
        int o = i / 3, c = i % 3;
        w[i] = Ws0[o * 6 + c];
    }
    __syncthreads();
    int ga = blockIdx.x * 256 + t;
    const float* a = g_anchors + (size_t)ga * 3;
    float x = a[0], y = a[1], z = a[2];
    float4* o = (float4*)(g_A + (size_t)ga * 64);
#pragma unroll
    for (int oo = 0; oo < 64; oo += 4) {
        float4 r;
        const float* w0 = w + oo * 3;
        r.x = w0[0] * x + w0[1] * y + w0[2] * z;
        r.y = w0[3] * x + w0[4] * y + w0[5] * z;
        r.z = w0[6] * x + w0[7] * y + w0[8] * z;
        r.w = w0[9] * x + w0[10] * y + w0[11] * z;
        o[oo >> 2] = r;
    }
}

// ---------------------------------------------------------------------------
// K2c: transpose Wt[j][o][r] -> WtT[j][r][o]; transpose Ws1[r][k] -> Ws1T[k][r]
// ---------------------------------------------------------------------------
__global__ void __launch_bounds__(256) transpose_weights(const float* __restrict__ Wt,
                                                         const float* __restrict__ Ws1) {
    int t = blockIdx.x * 256 + threadIdx.x;
    if (t < Jn * 256 * 128) {
        int j = t / (256 * 128);
        int rem = t % (256 * 128);
        int o = rem / 128, r = rem % 128;
        g_WtT[(j * 128 + r) * 256 + o] = Wt[t];
    }
    if (t < 128 * 64) {
        int r = t >> 6, k = t & 63;
        g_Ws1T[k * 128 + r] = Ws1[t];
    }
}

// ---------------------------------------------------------------------------
// K3: ball query. One warp per anchor; first-32 in ascending index order,
// pad with first found (0 if none).
// ---------------------------------------------------------------------------
__global__ void __launch_bounds__(256) ball_query_kernel(const float* __restrict__ xyzs) {
    int combo = blockIdx.y;  // ((b*8+s)*3 + j)
    int j = combo % 3;
    int bs = combo / 3;
    int b = bs >> 3, s = bs & 7;
    int g = s - 1 + j;
    g = g < 0 ? 0 : (g > 7 ? 7 : g);
    int wid = threadIdx.x >> 5, lane = threadIdx.x & 31;
    int m = blockIdx.x * 8 + wid;

    const float* pts = xyzs + (size_t)(b * 8 + g) * Nn * 3;
    const float* anc = g_anchors + ((size_t)bs * Mn + m) * 3;
    float ax = anc[0], ay = anc[1], az = anc[2];
    int* out = g_idx + ((size_t)combo * Mn + m) * Kn;

    int found = 0, first = -1;
    unsigned lt = (1u << lane) - 1u;
    for (int base = 0; base < Nn && found < Kn; base += 32) {
        int n = base + lane;
        const float* pp = pts + 3 * n;
        float dx = __fsub_rn(pp[0], ax);
        float dy = __fsub_rn(pp[1], ay);
        float dz = __fsub_rn(pp[2], az);
        float d2 = __fadd_rn(__fadd_rn(__fmul_rn(dx, dx), __fmul_rn(dy, dy)),
                             __fmul_rn(dz, dz));
        bool pred = d2 < 0.25f;
        unsigned msk = __ballot_sync(0xffffffffu, pred);
        if (first < 0 && msk) first = base + (__ffs(msk) - 1);
        int pos = found + __popc(msk & lt);
        if (pred && pos < Kn) out[pos] = n;
        found += __popc(msk);
    }
    if (found < Kn) {
        int pad = first < 0 ? 0 : first;
        for (int p = found + lane; p < Kn; p += 32) out[p] = pad;
    }
}

// ---------------------------------------------------------------------------
// K4: layer-1 GEMM fused with h0 generation (relu(P[n]-A[m])), relu, 32-way
// max pool. Tile: 128 rows x 128 cols (4 anchors), K=64 in 2 chunks of 32.
// 256 threads, 8x8 microtile. Static smem = 48KB exactly:
//   Wsh[64][128] = 32KB (persistent), Hsh[32][128] = 16KB (per-chunk),
//   hmax scratch aliased over Wsh after the mainloop.
// ---------------------------------------------------------------------------
__global__ void __launch_bounds__(256) mlp_kernel() {
    __shared__ float Wsh[64 * 128];  // [k][r]
    __shared__ float Hsh[32 * 128];  // [k-in-chunk][c]

    int t = threadIdx.x;
    int combo = blockIdx.y;
    int j = combo % 3;
    int bs = combo / 3;
    int b = bs >> 3, s = bs & 7;
    int g = s - 1 + j;
    g = g < 0 ? 0 : (g > 7 ? 7 : g);

    // load Ws1T (already [k][r]) — coalesced LDG + conflict-free STS
    for (int i = t; i < 64 * 128; i += 256) Wsh[i] = g_Ws1T[i];

    // per-thread H-producer metadata (column owned across both chunks)
    int col = t & 127;
    int kq = t >> 7;  // 0..1 -> k-subrange kq*16 .. +15 within chunk
    int gcol = blockIdx.x * 128 + col;
    int m = gcol >> 5;
    int knb = gcol & 31;
    int n = g_idx[((size_t)combo * Mn + m) * Kn + knb];
    const float4* Prow = (const float4*)(g_P + ((size_t)(b * 8 + g) * Nn + n) * 64);
    const float4* Arow = (const float4*)(g_A + ((size_t)bs * Mn + m) * 64);

    int r0 = (t >> 4) << 3;  // 0..120
    int c0 = (t & 15) << 3;  // 0..120
    float acc[8][8];
#pragma unroll
    for (int a = 0; a < 8; a++)
#pragma unroll
        for (int bb = 0; bb < 8; bb++) acc[a][bb] = 0.f;

#pragma unroll
    for (int kc = 0; kc < 2; kc++) {
        // produce H chunk: k in [kc*32, kc*32+32)
#pragma unroll
        for (int q = 0; q < 4; q++) {
            float4 p4 = Prow[kc * 8 + kq * 4 + q];
            float4 a4 = Arow[kc * 8 + kq * 4 + q];
            int k = kq * 16 + q * 4;
            Hsh[(k + 0) * 128 + col] = fmaxf(p4.x - a4.x, 0.f);
            Hsh[(k + 1) * 128 + col] = fmaxf(p4.y - a4.y, 0.f);
            Hsh[(k + 2) * 128 + col] = fmaxf(p4.z - a4.z, 0.f);
            Hsh[(k + 3) * 128 + col] = fmaxf(p4.w - a4.w, 0.f);
        }
        __syncthreads();

        const float* Wk = Wsh + kc * 32 * 128;
#pragma unroll 8
        for (int k = 0; k < 32; k++) {
            float4 a0 = *(const float4*)&Wk[k * 128 + r0];
            float4 a1 = *(const float4*)&Wk[k * 128 + r0 + 4];
            float4 b0 = *(const float4*)&Hsh[k * 128 + c0];
            float4 b1 = *(const float4*)&Hsh[k * 128 + c0 + 4];
            float av[8] = {a0.x, a0.y, a0.z, a0.w, a1.x, a1.y, a1.z, a1.w};
            float bv[8] = {b0.x, b0.y, b0.z, b0.w, b1.x, b1.y, b1.z, b1.w};
#pragma unroll
            for (int rr = 0; rr < 8; rr++)
#pragma unroll
                for (int cc = 0; cc < 8; cc++) acc[rr][cc] += av[rr] * bv[cc];
        }
        __syncthreads();
    }

    // epilogue: alias hmax scratch over Wsh (done with weights)
    int* hmi = (int*)Wsh;  // [4 anchors][128 rows]
    for (int i = t; i < 512; i += 256) hmi[i] = 0;
    __syncthreads();
    int alocal = c0 >> 5;  // this thread's 8 cols sit in one anchor
#pragma unroll
    for (int rr = 0; rr < 8; rr++) {
        float mx = acc[rr][0];
#pragma unroll
        for (int cc = 1; cc < 8; cc++) mx = fmaxf(mx, acc[rr][cc]);
        mx = fmaxf(mx, 0.f);
        atomicMax(&hmi[alocal * 128 + r0 + rr], __float_as_int(mx));
    }
    __syncthreads();

    // write [combo][m][r] — coalesced
    int mbase = blockIdx.x * 4;
    for (int i = t; i < 512; i += 256) {
        int a = i >> 7, r = i & 127;
        g_hmax[((size_t)combo * Mn + mbase + a) * 128 + r] = __int_as_float(hmi[a * 128 + r]);
    }
}

// ---------------------------------------------------------------------------
// K5: out[b][s][o][m] = sum_j relu(Wt[j] @ hmax[b][s][j]).
// Block: 256 output rows x 32 anchors. hsh reads are warp-broadcast LDS.128.
// ---------------------------------------------------------------------------
__global__ void __launch_bounds__(256) wt_kernel(float* __restrict__ outf) {
    __shared__ float hsh[32 * 128];
    int t = threadIdx.x;
    int bs = blockIdx.y;
    int mbase = blockIdx.x * 32;

    float tot[32];
#pragma unroll
    for (int i = 0; i < 32; i++) tot[i] = 0.f;

    for (int j = 0; j < 3; j++) {
        const float* hb = g_hmax + ((size_t)(bs * 3 + j) * Mn + mbase) * 128;
        for (int i = t; i < 32 * 128; i += 256) hsh[i] = hb[i];
        __syncthreads();

        float acc[32];
#pragma unroll
        for (int i = 0; i < 32; i++) acc[i] = 0.f;

        const float* wtb = g_WtT + (size_t)j * 128 * 256 + t;
        for (int r = 0; r < 128; r += 4) {
            float w0 = wtb[(r + 0) * 256];
            float w1 = wtb[(r + 1) * 256];
            float w2 = wtb[(r + 2) * 256];
            float w3 = wtb[(r + 3) * 256];
#pragma unroll
            for (int mm = 0; mm < 32; mm++) {
                float4 h = *(const float4*)&hsh[mm * 128 + r];
                acc[mm] += w0 * h.x + w1 * h.y + w2 * h.z + w3 * h.w;
            }
        }
#pragma unroll
        for (int i = 0; i < 32; i++) tot[i] += fmaxf(acc[i], 0.f);
        __syncthreads();
    }

    float4* o = (float4*)(outf + ((size_t)bs * 256 + t) * Mn + mbase);
#pragma unroll
    for (int q = 0; q < 8; q++) {
        float4 r;
        r.x = tot[4 * q + 0];
        r.y = tot[4 * q + 1];
        r.z = tot[4 * q + 2];
        r.w = tot[4 * q + 3];
        o[q] = r;
    }
}

// ---------------------------------------------------------------------------
extern "C" void kernel_launch(void* const* d_in, const int* in_sizes, int n_in,
                              void* d_out, int out_size) {
    const float* xyzs = (const float*)d_in[0];
    const float* feats = (const float*)d_in[1];
    const float* Ws0 = (const float*)d_in[2];
    const float* Ws1 = (const float*)d_in[3];
    const float* Wt = (const float*)d_in[4];
    float* out = (float*)d_out;

    const int XYZ_TOTAL = Bn * Sn * Mn * 3;  // 196608

    fps_kernel<<<Bn * Sn, 1024>>>(xyzs, out);
    compute_P<<<Bn * 8 * Nn / 256, 256>>>(xyzs, feats, Ws0);
    transpose_weights<<<(Jn * 256 * 128 + 255) / 256, 256>>>(Wt, Ws1);
    compute_A<<<Bn * Sn * Mn / 256, 256>>>(Ws0);
    ball_query_kernel<<<dim3(Mn / 8, Bn * Sn * Jn), 256>>>(xyzs);
    mlp_kernel<<<dim3(Mn * Kn / 128, Bn * Sn * Jn), 256>>>();
    wt_kernel<<<dim3(Mn / 32, Bn * Sn), 256>>>(out + XYZ_TOTAL);
}

// round 4
// speedup vs baseline: 1.3184x; 1.3184x over previous
#include <cuda_runtime.h>
#include <cuda_bf16.h>

// Problem constants
#define Bn 4
#define Ln 8
#define Nn 4096
#define Mn 2048
#define Kn 32
#define Sn 8
#define Jn 3

// Staging buffers (device globals; no runtime allocation)
__device__ float g_anchors[Bn * Sn * Mn * 3];
__device__ float g_P[Bn * 8 * Nn * 64];
__device__ float g_A[Bn * Sn * Mn * 64];
__device__ int   g_idx[Bn * Sn * Jn * Mn * Kn];
__device__ float g_hmax[Bn * Sn * Jn * Mn * 128];        // [combo][m][r]
__device__ float g_WtT[Jn * 128 * 256];                  // Wt transposed [j][r][o]
__device__ __nv_bfloat16 g_Ws1hi[128 * 64];              // Ws1 hi, [r][k]
__device__ __nv_bfloat16 g_Ws1lo[128 * 64];              // Ws1 lo, [r][k]

// ---------------------------------------------------------------------------
// K1: FPS. One block per (b,s). 1024 threads, 4 pts each, coords carried
// through the argmax reduction (2 barriers/iter). No-FMA arithmetic.
// ---------------------------------------------------------------------------
__global__ void __launch_bounds__(1024) fps_kernel(const float* __restrict__ xyzs,
                                                   float* __restrict__ out_xyz) {
    int bs = blockIdx.x;
    const float* xyz = xyzs + (size_t)bs * Nn * 3;
    __shared__ float rv[32], rx[32], ry[32], rz[32];
    __shared__ int ri[32];
    __shared__ float scx, scy, scz;

    int t = threadIdx.x;
    int lane = t & 31, wid = t >> 5;

    float px[4], py[4], pz[4], pd[4];
#pragma unroll
    for (int i = 0; i < 4; i++) {
        int p = t + i * 1024;
        px[i] = xyz[3 * p]; py[i] = xyz[3 * p + 1]; pz[i] = xyz[3 * p + 2];
        pd[i] = 1e10f;
    }
    if (t == 0) { scx = px[0]; scy = py[0]; scz = pz[0]; }
    __syncthreads();

    float* oanc = g_anchors + (size_t)bs * Mn * 3;
    float* oxyz = out_xyz + (size_t)bs * Mn * 3;

    for (int m = 0; m < Mn; m++) {
        float cx = scx, cy = scy, cz = scz;
        if (t == 0) {
            oanc[3 * m] = cx; oanc[3 * m + 1] = cy; oanc[3 * m + 2] = cz;
            oxyz[3 * m] = cx; oxyz[3 * m + 1] = cy; oxyz[3 * m + 2] = cz;
        }
        float best = -1.0f, bx = 0.f, by = 0.f, bz = 0.f;
        int bi = 0;
#pragma unroll
        for (int i = 0; i < 4; i++) {
            float dx = __fsub_rn(px[i], cx);
            float dy = __fsub_rn(py[i], cy);
            float dz = __fsub_rn(pz[i], cz);
            float d = __fadd_rn(__fadd_rn(__fmul_rn(dx, dx), __fmul_rn(dy, dy)),
                                __fmul_rn(dz, dz));
            float nd = fminf(pd[i], d);
            pd[i] = nd;
            if (nd > best) { best = nd; bi = t + i * 1024; bx = px[i]; by = py[i]; bz = pz[i]; }
        }
#pragma unroll
        for (int off = 16; off > 0; off >>= 1) {
            float v = __shfl_xor_sync(0xffffffffu, best, off);
            int j2 = __shfl_xor_sync(0xffffffffu, bi, off);
            float x2 = __shfl_xor_sync(0xffffffffu, bx, off);
            float y2 = __shfl_xor_sync(0xffffffffu, by, off);
            float z2 = __shfl_xor_sync(0xffffffffu, bz, off);
            if (v > best || (v == best && j2 < bi)) { best = v; bi = j2; bx = x2; by = y2; bz = z2; }
        }
        if (lane == 0) { rv[wid] = best; ri[wid] = bi; rx[wid] = bx; ry[wid] = by; rz[wid] = bz; }
        __syncthreads();
        if (wid == 0) {
            best = rv[lane]; bi = ri[lane]; bx = rx[lane]; by = ry[lane]; bz = rz[lane];
#pragma unroll
            for (int off = 16; off > 0; off >>= 1) {
                float v = __shfl_xor_sync(0xffffffffu, best, off);
                int j2 = __shfl_xor_sync(0xffffffffu, bi, off);
                float x2 = __shfl_xor_sync(0xffffffffu, bx, off);
                float y2 = __shfl_xor_sync(0xffffffffu, by, off);
                float z2 = __shfl_xor_sync(0xffffffffu, bz, off);
                if (v > best || (v == best && j2 < bi)) { best = v; bi = j2; bx = x2; by = y2; bz = z2; }
            }
            if (lane == 0) { scx = bx; scy = by; scz = bz; }
        }
        __syncthreads();
    }
}

// ---------------------------------------------------------------------------
// K2a: P = Ws0[:,0:3]@xyz + Ws0[:,3:6]@feat per point
// ---------------------------------------------------------------------------
__global__ void __launch_bounds__(256) compute_P(const float* __restrict__ xyzs,
                                                 const float* __restrict__ feats,
                                                 const float* __restrict__ Ws0) {
    __shared__ float w[64 * 6];
    int t = threadIdx.x;
    for (int i = t; i < 64 * 6; i += 256) w[i] = Ws0[i];
    __syncthreads();

    int gp = blockIdx.x * 256 + t;
    int n = gp & (Nn - 1);
    int bf = gp >> 12;
    const float* p = xyzs + (size_t)gp * 3;
    float x = p[0], y = p[1], z = p[2];
    const float* f = feats + (size_t)bf * 3 * Nn + n;
    float f0 = f[0], f1 = f[Nn], f2 = f[2 * Nn];
    float4* o = (float4*)(g_P + (size_t)gp * 64);
#pragma unroll
    for (int oo = 0; oo < 64; oo += 4) {
        float4 r;
        const float* w0 = w + oo * 6;
        r.x = w0[0] * x + w0[1] * y + w0[2] * z + w0[3] * f0 + w0[4] * f1 + w0[5] * f2;
        r.y = w0[6] * x + w0[7] * y + w0[8] * z + w0[9] * f0 + w0[10] * f1 + w0[11] * f2;
        r.z = w0[12] * x + w0[13] * y + w0[14] * z + w0[15] * f0 + w0[16] * f1 + w0[17] * f2;
        r.w = w0[18] * x + w0[19] * y + w0[20] * z + w0[21] * f0 + w0[22] * f1 + w0[23] * f2;
        o[oo >> 2] = r;
    }
}

// ---------------------------------------------------------------------------
// K2b: A = Ws0[:,0:3] @ anchor
// ---------------------------------------------------------------------------
__global__ void __launch_bounds__(256) compute_A(const float* __restrict__ Ws0) {
    __shared__ float w[64 * 3];
    int t = threadIdx.x;
    for (int i = t; i < 64 * 3; i += 256) {
        int o = i / 3, c = i % 3;
        w[i] = Ws0[o * 6 + c];
    }
    __syncthreads();
    int ga = blockIdx.x * 256 + t;
    const float* a = g_anchors + (size_t)ga * 3;
    float x = a[0], y = a[1], z = a[2];
    float4* o = (float4*)(g_A + (size_t)ga * 64);
#pragma unroll
    for (int oo = 0; oo < 64; oo += 4) {
        float4 r;
        const float* w0 = w + oo * 3;
        r.x = w0[0] * x + w0[1] * y + w0[2] * z;
        r.y = w0[3] * x + w0[4] * y + w0[5] * z;
        r.z = w0[6] * x + w0[7] * y + w0[8] * z;
        r.w = w0[9] * x + w0[10] * y + w0[11] * z;
        o[oo >> 2] = r;
    }
}

// ---------------------------------------------------------------------------
// K2c: transpose Wt -> WtT; split Ws1 into bf16 hi/lo ([r][k], plain layout)
// ---------------------------------------------------------------------------
__global__ void __launch_bounds__(256) transpose_weights(const float* __restrict__ Wt,
                                                         const float* __restrict__ Ws1) {
    int t = blockIdx.x * 256 + threadIdx.x;
    if (t < Jn * 256 * 128) {
        int j = t / (256 * 128);
        int rem = t % (256 * 128);
        int o = rem / 128, r = rem % 128;
        g_WtT[(j * 128 + r) * 256 + o] = Wt[t];
    }
    if (t < 128 * 64) {
        float w = Ws1[t];
        __nv_bfloat16 hi = __float2bfloat16_rn(w);
        __nv_bfloat16 lo = __float2bfloat16_rn(w - __bfloat162float(hi));
        g_Ws1hi[t] = hi;
        g_Ws1lo[t] = lo;
    }
}

// ---------------------------------------------------------------------------
// K3: ball query (unchanged)
// ---------------------------------------------------------------------------
__global__ void __launch_bounds__(256) ball_query_kernel(const float* __restrict__ xyzs) {
    int combo = blockIdx.y;
    int j = combo % 3;
    int bs = combo / 3;
    int b = bs >> 3, s = bs & 7;
    int g = s - 1 + j;
    g = g < 0 ? 0 : (g > 7 ? 7 : g);
    int wid = threadIdx.x >> 5, lane = threadIdx.x & 31;
    int m = blockIdx.x * 8 + wid;

    const float* pts = xyzs + (size_t)(b * 8 + g) * Nn * 3;
    const float* anc = g_anchors + ((size_t)bs * Mn + m) * 3;
    float ax = anc[0], ay = anc[1], az = anc[2];
    int* out = g_idx + ((size_t)combo * Mn + m) * Kn;

    int found = 0, first = -1;
    unsigned lt = (1u << lane) - 1u;
    for (int base = 0; base < Nn && found < Kn; base += 32) {
        int n = base + lane;
        const float* pp = pts + 3 * n;
        float dx = __fsub_rn(pp[0], ax);
        float dy = __fsub_rn(pp[1], ay);
        float dz = __fsub_rn(pp[2], az);
        float d2 = __fadd_rn(__fadd_rn(__fmul_rn(dx, dx), __fmul_rn(dy, dy)),
                             __fmul_rn(dz, dz));
        bool pred = d2 < 0.25f;
        unsigned msk = __ballot_sync(0xffffffffu, pred);
        if (first < 0 && msk) first = base + (__ffs(msk) - 1);
        int pos = found + __popc(msk & lt);
        if (pred && pos < Kn) out[pos] = n;
        found += __popc(msk);
    }
    if (found < Kn) {
        int pad = first < 0 ? 0 : first;
        for (int p = found + lane; p < Kn; p += 32) out[p] = pad;
    }
}

// ---------------------------------------------------------------------------
// K4: layer-1 GEMM on tensor cores (bf16 hi/lo split, 3 mma products),
// fused with h0 generation and 32-way max pool. Tile: 128 rows x 64 cols,
// K=64. 8 warps; warp w owns m-rows [16w,16w+16). Epilogue via quad shuffles.
// Static smem exactly 48KB. XOR-16B swizzle for conflict-free ldmatrix.
// ---------------------------------------------------------------------------
__device__ __forceinline__ void mma_bf16(float c[4], const unsigned a[4],
                                         unsigned b0, unsigned b1) {
    asm volatile(
        "mma.sync.aligned.m16n8k16.row.col.f32.bf16.bf16.f32 "
        "{%0,%1,%2,%3}, {%4,%5,%6,%7}, {%8,%9}, {%0,%1,%2,%3};"
        : "+f"(c[0]), "+f"(c[1]), "+f"(c[2]), "+f"(c[3])
        : "r"(a[0]), "r"(a[1]), "r"(a[2]), "r"(a[3]), "r"(b0), "r"(b1));
}

__device__ __forceinline__ void ldsm4(unsigned r[4], unsigned saddr) {
    asm volatile(
        "ldmatrix.sync.aligned.m8n8.x4.shared.b16 {%0,%1,%2,%3}, [%4];"
        : "=r"(r[0]), "=r"(r[1]), "=r"(r[2]), "=r"(r[3])
        : "r"(saddr));
}

__global__ void __launch_bounds__(256) mlp_kernel() {
    __shared__ __align__(16) __nv_bfloat16 Ahi[128 * 64];  // 16KB  [r][k] swizzled
    __shared__ __align__(16) __nv_bfloat16 Alo[128 * 64];  // 16KB
    __shared__ __align__(16) __nv_bfloat16 Bhi[64 * 64];   //  8KB  [col][k] swizzled
    __shared__ __align__(16) __nv_bfloat16 Blo[64 * 64];   //  8KB

    int t = threadIdx.x;
    int lane = t & 31, w = t >> 5;
    int combo = blockIdx.y;
    int j = combo % 3;
    int bs = combo / 3;
    int b = bs >> 3, s = bs & 7;
    int g = s - 1 + j;
    g = g < 0 ? 0 : (g > 7 ? 7 : g);

    // --- load W hi/lo into smem with 16B-chunk XOR swizzle ---
    {
        const uint4* gh = (const uint4*)g_Ws1hi;  // 1024 x 16B
        const uint4* gl = (const uint4*)g_Ws1lo;
        uint4* sh = (uint4*)Ahi;
        uint4* sl = (uint4*)Alo;
        for (int i = t; i < 1024; i += 256) {
            int r = i >> 3, c = i & 7;
            int sc = (r << 3) + (c ^ (r & 7));
            sh[sc] = gh[i];
            sl[sc] = gl[i];
        }
    }

    // --- produce H hi/lo: col = anchor-local col, 16 k-values per thread ---
    {
        int col = t & 63;
        int kq = t >> 6;  // 0..3 -> k range [kq*16, kq*16+16)
        int gcol = blockIdx.x * 64 + col;
        int m = gcol >> 5;
        int knb = gcol & 31;
        int n = g_idx[((size_t)combo * Mn + m) * Kn + knb];
        const float4* Prow = (const float4*)(g_P + ((size_t)(b * 8 + g) * Nn + n) * 64);
        const float4* Arow = (const float4*)(g_A + ((size_t)bs * Mn + m) * 64);
        char* bh = (char*)Bhi;
        char* bl = (char*)Blo;
#pragma unroll
        for (int q = 0; q < 4; q++) {
            float4 p4 = Prow[kq * 4 + q];
            float4 a4 = Arow[kq * 4 + q];
            float h0 = fmaxf(p4.x - a4.x, 0.f);
            float h1 = fmaxf(p4.y - a4.y, 0.f);
            float h2 = fmaxf(p4.z - a4.z, 0.f);
            float h3 = fmaxf(p4.w - a4.w, 0.f);
            __nv_bfloat162 hiA, hiB, loA, loB;
            hiA.x = __float2bfloat16_rn(h0); hiA.y = __float2bfloat16_rn(h1);
            hiB.x = __float2bfloat16_rn(h2); hiB.y = __float2bfloat16_rn(h3);
            loA.x = __float2bfloat16_rn(h0 - __bfloat162float(hiA.x));
            loA.y = __float2bfloat16_rn(h1 - __bfloat162float(hiA.y));
            loB.x = __float2bfloat16_rn(h2 - __bfloat162float(hiB.x));
            loB.y = __float2bfloat16_rn(h3 - __bfloat162float(hiB.y));
            int k0 = kq * 16 + q * 4;
            int chunk = k0 >> 3;
            int off = col * 128 + ((chunk ^ (col & 7)) << 4) + ((k0 & 7) << 1);
            uint2 vh, vl;
            vh.x = *(unsigned*)&hiA; vh.y = *(unsigned*)&hiB;
            vl.x = *(unsigned*)&loA; vl.y = *(unsigned*)&loB;
            *(uint2*)(bh + off) = vh;
            *(uint2*)(bl + off) = vl;
        }
    }
    __syncthreads();

    unsigned sAhi = (unsigned)__cvta_generic_to_shared(Ahi);
    unsigned sAlo = (unsigned)__cvta_generic_to_shared(Alo);
    unsigned sBhi = (unsigned)__cvta_generic_to_shared(Bhi);
    unsigned sBlo = (unsigned)__cvta_generic_to_shared(Blo);

    // --- hoist A fragments (4 ksteps x 4 regs, hi+lo) ---
    unsigned ahi[4][4], alo[4][4];
    {
        int m0 = w * 16;
        int r = m0 + (lane & 15);
#pragma unroll
        for (int ks = 0; ks < 4; ks++) {
            int chunk = ks * 2 + (lane >> 4);
            unsigned off = r * 128 + ((chunk ^ (r & 7)) << 4);
            ldsm4(ahi[ks], sAhi + off);
            ldsm4(alo[ks], sAlo + off);
        }
    }

    float acc[8][4];
#pragma unroll
    for (int nt = 0; nt < 8; nt++)
#pragma unroll
        for (int i = 0; i < 4; i++) acc[nt][i] = 0.f;

    // B ldmatrix address pattern: x4 covers n-tiles (2p, 2p+1) for one kstep
    int brow_base = (lane & 7) + ((lane & 16) >> 1);  // + p*16
    int bksel = (lane >> 3) & 1;                       // chunk low/high

#pragma unroll
    for (int ks = 0; ks < 4; ks++) {
        unsigned bhi[4][2], blo[4][2];
#pragma unroll
        for (int p = 0; p < 4; p++) {
            int r = p * 16 + brow_base;
            int chunk = ks * 2 + bksel;
            unsigned off = r * 128 + ((chunk ^ (r & 7)) << 4);
            unsigned tmp[4];
            ldsm4(tmp, sBhi + off);
            bhi[p][0] = tmp[0]; bhi[p][1] = tmp[1];
            // regs 2,3 belong to n-tile 2p+1 — stash via second pair
            unsigned tmp2[4];
            tmp2[0] = tmp[2]; tmp2[1] = tmp[3];
            ldsm4(tmp, sBlo + off);
            blo[p][0] = tmp[0]; blo[p][1] = tmp[1];
            // mma for n-tiles 2p and 2p+1
            mma_bf16(acc[2 * p], ahi[ks], bhi[p][0], bhi[p][1]);
            mma_bf16(acc[2 * p], ahi[ks], blo[p][0], blo[p][1]);
            mma_bf16(acc[2 * p], alo[ks], bhi[p][0], bhi[p][1]);
            mma_bf16(acc[2 * p + 1], ahi[ks], tmp2[0], tmp2[1]);
            mma_bf16(acc[2 * p + 1], ahi[ks], tmp[2], tmp[3]);
            mma_bf16(acc[2 * p + 1], alo[ks], tmp2[0], tmp2[1]);
        }
    }
    __syncthreads();

    // --- epilogue: per-anchor max over 32 cols via quad shuffles ---
    float* hm = (float*)Bhi;  // scratch [2][128]
#pragma unroll
    for (int a = 0; a < 2; a++) {
        float m0 = -1e30f, m1 = -1e30f;
#pragma unroll
        for (int nt = a * 4; nt < a * 4 + 4; nt++) {
            m0 = fmaxf(m0, fmaxf(acc[nt][0], acc[nt][1]));
            m1 = fmaxf(m1, fmaxf(acc[nt][2], acc[nt][3]));
        }
        m0 = fmaxf(m0, __shfl_xor_sync(0xffffffffu, m0, 1));
        m0 = fmaxf(m0, __shfl_xor_sync(0xffffffffu, m0, 2));
        m1 = fmaxf(m1, __shfl_xor_sync(0xffffffffu, m1, 1));
        m1 = fmaxf(m1, __shfl_xor_sync(0xffffffffu, m1, 2));
        if ((lane & 3) == 0) {
            int grp = lane >> 2;
            hm[a * 128 + w * 16 + grp] = fmaxf(m0, 0.f);
            hm[a * 128 + w * 16 + grp + 8] = fmaxf(m1, 0.f);
        }
    }
    __syncthreads();

    int mbase = blockIdx.x * 2;
    {
        int a = t >> 7, r = t & 127;
        g_hmax[((size_t)combo * Mn + mbase + a) * 128 + r] = hm[a * 128 + r];
    }
}

// ---------------------------------------------------------------------------
// K5: out = sum_j relu(Wt[j] @ hmax[j]) (unchanged)
// ---------------------------------------------------------------------------
__global__ void __launch_bounds__(256) wt_kernel(float* __restrict__ outf) {
    __shared__ float hsh[32 * 128];
    int t = threadIdx.x;
    int bs = blockIdx.y;
    int mbase = blockIdx.x * 32;

    float tot[32];
#pragma unroll
    for (int i = 0; i < 32; i++) tot[i] = 0.f;

    for (int j = 0; j < 3; j++) {
        const float* hb = g_hmax + ((size_t)(bs * 3 + j) * Mn + mbase) * 128;
        for (int i = t; i < 32 * 128; i += 256) hsh[i] = hb[i];
        __syncthreads();

        float acc[32];
#pragma unroll
        for (int i = 0; i < 32; i++) acc[i] = 0.f;

        const float* wtb = g_WtT + (size_t)j * 128 * 256 + t;
        for (int r = 0; r < 128; r += 4) {
            float w0 = wtb[(r + 0) * 256];
            float w1 = wtb[(r + 1) * 256];
            float w2 = wtb[(r + 2) * 256];
            float w3 = wtb[(r + 3) * 256];
#pragma unroll
            for (int mm = 0; mm < 32; mm++) {
                float4 h = *(const float4*)&hsh[mm * 128 + r];
                acc[mm] += w0 * h.x + w1 * h.y + w2 * h.z + w3 * h.w;
            }
        }
#pragma unroll
        for (int i = 0; i < 32; i++) tot[i] += fmaxf(acc[i], 0.f);
        __syncthreads();
    }

    float4* o = (float4*)(outf + ((size_t)bs * 256 + t) * Mn + mbase);
#pragma unroll
    for (int q = 0; q < 8; q++) {
        float4 r;
        r.x = tot[4 * q + 0];
        r.y = tot[4 * q + 1];
        r.z = tot[4 * q + 2];
        r.w = tot[4 * q + 3];
        o[q] = r;
    }
}

// ---------------------------------------------------------------------------
extern "C" void kernel_launch(void* const* d_in, const int* in_sizes, int n_in,
                              void* d_out, int out_size) {
    const float* xyzs = (const float*)d_in[0];
    const float* feats = (const float*)d_in[1];
    const float* Ws0 = (const float*)d_in[2];
    const float* Ws1 = (const float*)d_in[3];
    const float* Wt = (const float*)d_in[4];
    float* out = (float*)d_out;

    const int XYZ_TOTAL = Bn * Sn * Mn * 3;  // 196608

    fps_kernel<<<Bn * Sn, 1024>>>(xyzs, out);
    compute_P<<<Bn * 8 * Nn / 256, 256>>>(xyzs, feats, Ws0);
    transpose_weights<<<(Jn * 256 * 128 + 255) / 256, 256>>>(Wt, Ws1);
    compute_A<<<Bn * Sn * Mn / 256, 256>>>(Ws0);
    ball_query_kernel<<<dim3(Mn / 8, Bn * Sn * Jn), 256>>>(xyzs);
    mlp_kernel<<<dim3(Mn * Kn / 64, Bn * Sn * Jn), 256>>>();
    wt_kernel<<<dim3(Mn / 32, Bn * Sn), 256>>>(out + XYZ_TOTAL);
}